// round 13
// baseline (speedup 1.0000x reference)
#include <cuda_runtime.h>
#include <cstdint>

#define N_NODES 100000
#define N_EDGES 1600000
#define F_IN    100
#define F_H     32
#define GROWS   128    // rows per gemm block
#define XPAD    103    // xs row stride (floats): bank-conflict-free broadcast
#define SCAN_BS 512
#define SCAN_NB ((N_NODES + SCAN_BS - 1) / SCAN_BS)   // 196

typedef unsigned long long ull;

// ---------------- scratch (static device globals; no runtime allocs) ---------
__device__ int   g_cnt [N_NODES];     // in-degree (excl self loop)
__device__ int   g_rowptr[N_NODES];   // CSR row starts
__device__ int   g_cur [N_NODES];     // build cursor
__device__ int   g_col [N_EDGES];     // CSR column (src) list
__device__ float g_dinv[N_NODES];
__device__ __align__(16) float g_hs [(size_t)N_NODES * F_H];  // h * dinv[src]
__device__ __align__(16) float g_agg[(size_t)N_NODES * F_H];  // aggregate
__device__ int   g_bsum[SCAN_NB];
__device__ int   g_is32;

__device__ __forceinline__ int edge_at(const void* ei, size_t i, int is32) {
    if (is32) return ((const int*)ei)[i];
    return (int)((const long long*)ei)[i];
}

// packed fp32x2 helpers (sm_100+)
__device__ __forceinline__ void fma2(ull& d, ull a, ull b) {
    asm("fma.rn.f32x2 %0, %1, %2, %0;" : "+l"(d) : "l"(a), "l"(b));
}
__device__ __forceinline__ ull dup2(float v) {
    ull r; asm("mov.b64 %0, {%1, %1};" : "=l"(r) : "f"(v)); return r;
}
__device__ __forceinline__ void unpk(ull v, float& lo, float& hi) {
    asm("mov.b64 {%0, %1}, %2;" : "=f"(lo), "=f"(hi) : "l"(v));
}

// ---------------- K1: zero counters + dtype detection ------------------------
__global__ void k_init(const void* ei, int n_total, int n_nodes) {
    int i = blockIdx.x * blockDim.x + threadIdx.x;
    if (i < n_nodes) g_cnt[i] = 0;
    if (blockIdx.x == 0) {
        __shared__ int bad;
        if (threadIdx.x == 0) bad = 0;
        __syncthreads();
        int n_check = n_total < 2048 ? n_total : 2048;
        for (int j = threadIdx.x; j < n_check; j += blockDim.x) {
            long long v = ((const long long*)ei)[j];
            if (v < 0 || v >= (long long)n_nodes) atomicOr(&bad, 1);
        }
        __syncthreads();
        if (threadIdx.x == 0) g_is32 = bad;   // int64-read garbage => int32 data
    }
}

// ---------------- K2: in-degree histogram ------------------------------------
__global__ void k_hist(const void* __restrict__ edge_index, int n_edges) {
    int e = blockIdx.x * blockDim.x + threadIdx.x;
    if (e < n_edges) {
        int dst = edge_at(edge_index, (size_t)n_edges + e, g_is32);
        atomicAdd(&g_cnt[dst], 1);
    }
}

// ---------------- K3a: per-block sums of g_cnt -------------------------------
__global__ void k_scan_a(int n_nodes) {
    __shared__ int s[SCAN_BS];
    int t = threadIdx.x;
    int i = blockIdx.x * SCAN_BS + t;
    s[t] = (i < n_nodes) ? g_cnt[i] : 0;
    __syncthreads();
    for (int off = SCAN_BS / 2; off > 0; off >>= 1) {
        if (t < off) s[t] += s[t + off];
        __syncthreads();
    }
    if (t == 0) g_bsum[blockIdx.x] = s[0];
}

// ---------------- K3b: scan (self-computed block offset) -> rowptr, cur, dinv
__global__ void k_scan_c(int n_nodes, int nb) {
    __shared__ int s[SCAN_BS];
    __shared__ int red[SCAN_BS];
    int t = threadIdx.x;

    // block offset = sum of g_bsum[0 .. blockIdx.x)
    int partial = 0;
    for (int b = t; b < blockIdx.x; b += SCAN_BS) partial += g_bsum[b];
    red[t] = partial;
    __syncthreads();
    for (int off = SCAN_BS / 2; off > 0; off >>= 1) {
        if (t < off) red[t] += red[t + off];
        __syncthreads();
    }
    int block_off = red[0];

    int i = blockIdx.x * SCAN_BS + t;
    int c = (i < n_nodes) ? g_cnt[i] : 0;
    s[t] = c;
    __syncthreads();
    for (int off = 1; off < SCAN_BS; off <<= 1) {
        int u = (t >= off) ? s[t - off] : 0;
        __syncthreads();
        s[t] += u;
        __syncthreads();
    }
    if (i < n_nodes) {
        int rp = block_off + s[t] - c;            // exclusive scan value
        g_rowptr[i] = rp;
        g_cur[i]    = rp;
        g_dinv[i]   = rsqrtf(1.0f + (float)c);    // self-loop included
    }
}

// ---------------- K4: CSR build ----------------------------------------------
__global__ void k_build(const void* __restrict__ edge_index, int n_edges) {
    int e = blockIdx.x * blockDim.x + threadIdx.x;
    if (e < n_edges) {
        int is32 = g_is32;
        int src = edge_at(edge_index, e, is32);
        int dst = edge_at(edge_index, (size_t)n_edges + e, is32);
        int pos = atomicAdd(&g_cur[dst], 1);
        g_col[pos] = src;
    }
}

// ---------------- K5: GEMM h = x@W, f32x2, smem-staged x ---------------------
__global__ void __launch_bounds__(128) k_gemm(const float* __restrict__ x,
                                              const float* __restrict__ W,
                                              int n_nodes) {
    extern __shared__ __align__(16) float smem[];
    float* xs = smem;                      // GROWS * XPAD
    float* Ws = smem + GROWS * XPAD;       // F_IN * F_H
    int tid = threadIdx.x;
    int row0 = blockIdx.x * GROWS;
    int nrow = n_nodes - row0; if (nrow > GROWS) nrow = GROWS;

    const float4* W4 = (const float4*)W;
    for (int i = tid; i < (F_IN * F_H) / 4; i += 128)
        ((float4*)Ws)[i] = W4[i];
    const float4* x4 = (const float4*)x;
    for (int i = tid; i < nrow * (F_IN / 4); i += 128) {
        int r = i / (F_IN / 4), c = i % (F_IN / 4);
        float4 v = x4[(size_t)(row0 + r) * (F_IN / 4) + c];
        float* d = &xs[r * XPAD + c * 4];
        d[0] = v.x; d[1] = v.y; d[2] = v.z; d[3] = v.w;
    }
    __syncthreads();

    int rt = tid >> 2;
    int cq = tid & 3;
    int rbase = rt * 4;

    ull acc[4][4];
#pragma unroll
    for (int j = 0; j < 4; j++)
#pragma unroll
        for (int p = 0; p < 4; p++) acc[j][p] = 0ull;

    const ulonglong2* Wp = (const ulonglong2*)Ws;
    const float* xr = &xs[rbase * XPAD];

#pragma unroll 4
    for (int k = 0; k < F_IN; k++) {
        ulonglong2 wA = Wp[k * 8 + cq * 2];
        ulonglong2 wB = Wp[k * 8 + cq * 2 + 1];
#pragma unroll
        for (int j = 0; j < 4; j++) {
            ull a = dup2(xr[j * XPAD + k]);
            fma2(acc[j][0], a, wA.x);
            fma2(acc[j][1], a, wA.y);
            fma2(acc[j][2], a, wB.x);
            fma2(acc[j][3], a, wB.y);
        }
    }

#pragma unroll
    for (int j = 0; j < 4; j++) {
        int row = row0 + rbase + j;
        if (row >= n_nodes) break;
        float dinv = g_dinv[row];
        float o[8];
#pragma unroll
        for (int p = 0; p < 4; p++) unpk(acc[j][p], o[p * 2], o[p * 2 + 1]);
        float4 v0 = {o[0]*dinv, o[1]*dinv, o[2]*dinv, o[3]*dinv};
        float4 v1 = {o[4]*dinv, o[5]*dinv, o[6]*dinv, o[7]*dinv};
        size_t off = (size_t)row * F_H + cq * 8;
        *(float4*)&g_hs[off]     = v0;
        *(float4*)&g_hs[off + 4] = v1;
    }
}

// ---------------- K6: CSR gather-aggregate, 4-edge batched (MLP>=4) ----------
// 8 lanes per dst; lane g owns features g*4..g*4+3. acc init = hs[dst] (self).
__global__ void k_agg(int n_nodes) {
    int t = blockIdx.x * blockDim.x + threadIdx.x;
    int dst = t >> 3;
    int g = t & 7;
    if (dst >= n_nodes) return;

    const float4* hs4 = (const float4*)g_hs;
    float4 acc = __ldg(&hs4[(size_t)dst * 8 + g]);   // self-loop term

    int i   = g_rowptr[dst];
    int cnt = g_cnt[dst];
    int j = 0;
    for (; j + 4 <= cnt; j += 4) {
        int s0 = __ldg(&g_col[i + j]);
        int s1 = __ldg(&g_col[i + j + 1]);
        int s2 = __ldg(&g_col[i + j + 2]);
        int s3 = __ldg(&g_col[i + j + 3]);
        float4 v0 = __ldg(&hs4[(size_t)s0 * 8 + g]);
        float4 v1 = __ldg(&hs4[(size_t)s1 * 8 + g]);
        float4 v2 = __ldg(&hs4[(size_t)s2 * 8 + g]);
        float4 v3 = __ldg(&hs4[(size_t)s3 * 8 + g]);
        acc.x += v0.x + v1.x + v2.x + v3.x;
        acc.y += v0.y + v1.y + v2.y + v3.y;
        acc.z += v0.z + v1.z + v2.z + v3.z;
        acc.w += v0.w + v1.w + v2.w + v3.w;
    }
    for (; j < cnt; j++) {
        int s = __ldg(&g_col[i + j]);
        float4 v = __ldg(&hs4[(size_t)s * 8 + g]);
        acc.x += v.x; acc.y += v.y; acc.z += v.z; acc.w += v.w;
    }
    ((float4*)g_agg)[(size_t)dst * 8 + g] = acc;
}

// ---------------- K7: dinv scale + bias + relu + MLP + log_softmax -----------
__global__ void k_mlp(const float* __restrict__ b_conv,
                      const float* __restrict__ W1, const float* __restrict__ b1,
                      const float* __restrict__ W2, const float* __restrict__ b2,
                      const float* __restrict__ W3, const float* __restrict__ b3,
                      float* __restrict__ out, int n_nodes) {
    __shared__ float sW1[32 * 16], sb1[16];
    __shared__ float sW2[16 * 8],  sb2[8];
    __shared__ float sW3[8 * 10],  sb3[10];
    __shared__ float sbc[32];
    int tid = threadIdx.x;
    for (int i = tid; i < 32 * 16; i += blockDim.x) sW1[i] = W1[i];
    for (int i = tid; i < 16 * 8;  i += blockDim.x) sW2[i] = W2[i];
    for (int i = tid; i < 8 * 10;  i += blockDim.x) sW3[i] = W3[i];
    if (tid < 16) sb1[tid] = b1[tid];
    if (tid < 8)  sb2[tid] = b2[tid];
    if (tid < 10) sb3[tid] = b3[tid];
    if (tid < 32) sbc[tid] = b_conv[tid];
    __syncthreads();

    int node = blockIdx.x * blockDim.x + tid;
    if (node >= n_nodes) return;

    float dinv = g_dinv[node];
    float a[32];
    const float4* ag4 = (const float4*)(&g_agg[(size_t)node * F_H]);
#pragma unroll
    for (int q = 0; q < 8; q++) {
        float4 v = ag4[q];
        a[q * 4 + 0] = fmaxf(fmaf(v.x, dinv, sbc[q * 4 + 0]), 0.0f);
        a[q * 4 + 1] = fmaxf(fmaf(v.y, dinv, sbc[q * 4 + 1]), 0.0f);
        a[q * 4 + 2] = fmaxf(fmaf(v.z, dinv, sbc[q * 4 + 2]), 0.0f);
        a[q * 4 + 3] = fmaxf(fmaf(v.w, dinv, sbc[q * 4 + 3]), 0.0f);
    }

    float h1[16];
#pragma unroll
    for (int j = 0; j < 16; j++) {
        float s = sb1[j];
#pragma unroll
        for (int k = 0; k < 32; k++) s = fmaf(a[k], sW1[k * 16 + j], s);
        h1[j] = fmaxf(s, 0.0f);
    }
    float h2[8];
#pragma unroll
    for (int j = 0; j < 8; j++) {
        float s = sb2[j];
#pragma unroll
        for (int k = 0; k < 16; k++) s = fmaf(h1[k], sW2[k * 8 + j], s);
        h2[j] = fmaxf(s, 0.0f);
    }
    float z[10];
#pragma unroll
    for (int j = 0; j < 10; j++) {
        float s = sb3[j];
#pragma unroll
        for (int k = 0; k < 8; k++) s = fmaf(h2[k], sW3[k * 10 + j], s);
        z[j] = s;
    }
    float m = z[0];
#pragma unroll
    for (int j = 1; j < 10; j++) m = fmaxf(m, z[j]);
    float sum = 0.0f;
#pragma unroll
    for (int j = 0; j < 10; j++) sum += expf(z[j] - m);
    float lse = logf(sum) + m;
    float* op = out + (size_t)node * 10;
#pragma unroll
    for (int j = 0; j < 10; j++) op[j] = z[j] - lse;
}

// ---------------- launch -----------------------------------------------------
extern "C" void kernel_launch(void* const* d_in, const int* in_sizes, int n_in,
                              void* d_out, int out_size) {
    const float* x          = (const float*)d_in[0];
    const void*  edge_index = (const void*)d_in[1];
    const float* W_conv = (const float*)d_in[3];
    const float* b_conv = (const float*)d_in[4];
    const float* W1 = (const float*)d_in[5];
    const float* b1 = (const float*)d_in[6];
    const float* W2 = (const float*)d_in[7];
    const float* b2 = (const float*)d_in[8];
    const float* W3 = (const float*)d_in[9];
    const float* b3 = (const float*)d_in[10];
    float* out = (float*)d_out;

    int n_nodes = in_sizes[0] / F_IN;
    int n_edges = in_sizes[1] / 2;
    int nb = (n_nodes + SCAN_BS - 1) / SCAN_BS;

    const int gemm_smem = (GROWS * XPAD + F_IN * F_H) * (int)sizeof(float); // 64 KB
    static int attr_done = 0;
    if (!attr_done) {
        cudaFuncSetAttribute(k_gemm, cudaFuncAttributeMaxDynamicSharedMemorySize,
                             gemm_smem);
        attr_done = 1;
    }

    k_init<<<(n_nodes + 255) / 256, 256>>>(edge_index, in_sizes[1], n_nodes);
    k_hist<<<(n_edges + 255) / 256, 256>>>(edge_index, n_edges);
    k_scan_a<<<nb, SCAN_BS>>>(n_nodes);
    k_scan_c<<<nb, SCAN_BS>>>(n_nodes, nb);
    k_build<<<(n_edges + 255) / 256, 256>>>(edge_index, n_edges);
    k_gemm<<<(n_nodes + GROWS - 1) / GROWS, 128, gemm_smem>>>(x, W_conv, n_nodes);
    long long agg_threads = (long long)n_nodes * 8;
    k_agg<<<(int)((agg_threads + 255) / 256), 256>>>(n_nodes);
    k_mlp<<<(n_nodes + 127) / 128, 128>>>(b_conv, W1, b1, W2, b2, W3, b3,
                                          out, n_nodes);
}

// round 15
// speedup vs baseline: 1.1327x; 1.1327x over previous
#include <cuda_runtime.h>
#include <cstdint>

#define N_NODES 100000
#define N_EDGES 1600000
#define F_IN    100
#define F_H     32
#define GROWS   128    // rows per gemm block
#define XPAD    103    // xs row stride (floats): bank-conflict-free broadcast

typedef unsigned long long ull;

// ---------------- scratch (static device globals; no runtime allocs) ---------
__device__ float g_deg [N_NODES];
__device__ float g_dinv[N_NODES];
__device__ __align__(16) float g_hs [(size_t)N_NODES * F_H];  // h * dinv[src]
__device__ __align__(16) float g_agg[(size_t)N_NODES * F_H];  // aggregate
__device__ int   g_is32;                                      // 1 if edge_index is int32

__device__ __forceinline__ int edge_at(const void* ei, size_t i, int is32) {
    if (is32) return ((const int*)ei)[i];
    return (int)((const long long*)ei)[i];
}

// packed fp32x2 helpers (sm_100+)
__device__ __forceinline__ void fma2(ull& d, ull a, ull b) {
    asm("fma.rn.f32x2 %0, %1, %2, %0;" : "+l"(d) : "l"(a), "l"(b));
}
__device__ __forceinline__ ull dup2(float v) {
    ull r; asm("mov.b64 %0, {%1, %1};" : "=l"(r) : "f"(v)); return r;
}
__device__ __forceinline__ void unpk(ull v, float& lo, float& hi) {
    asm("mov.b64 {%0, %1}, %2;" : "=f"(lo), "=f"(hi) : "l"(v));
}

// ---------------- K1: deg init + dtype detection (block 0) -------------------
__global__ void k_init_deg(const void* ei, int n_total, int n_nodes) {
    int i = blockIdx.x * blockDim.x + threadIdx.x;
    if (i < n_nodes) g_deg[i] = 1.0f;
    if (blockIdx.x == 0) {
        __shared__ int bad;
        if (threadIdx.x == 0) bad = 0;
        __syncthreads();
        int n_check = n_total < 2048 ? n_total : 2048;
        for (int j = threadIdx.x; j < n_check; j += blockDim.x) {
            long long v = ((const long long*)ei)[j];
            if (v < 0 || v >= (long long)n_nodes) atomicOr(&bad, 1);
        }
        __syncthreads();
        if (threadIdx.x == 0) g_is32 = bad;   // int64-read garbage => int32 data
    }
}

// ---------------- K2: degree accumulation over edges -------------------------
__global__ void k_degree(const void* __restrict__ edge_index, int n_edges) {
    int e = blockIdx.x * blockDim.x + threadIdx.x;
    if (e < n_edges) {
        int dst = edge_at(edge_index, (size_t)n_edges + e, g_is32);
        atomicAdd(&g_deg[dst], 1.0f);
    }
}

// ---------------- K3: GEMM h = x@W, f32x2, smem-staged x ---------------------
// 128 threads; tile 128 rows x 32 cols; thread = 4 rows x 8 cols. 64 KB smem.
__global__ void __launch_bounds__(128) k_gemm(const float* __restrict__ x,
                                              const float* __restrict__ W,
                                              int n_nodes) {
    extern __shared__ __align__(16) float smem[];
    float* xs = smem;                      // GROWS * XPAD
    float* Ws = smem + GROWS * XPAD;       // F_IN * F_H
    int tid = threadIdx.x;
    int row0 = blockIdx.x * GROWS;
    int nrow = n_nodes - row0; if (nrow > GROWS) nrow = GROWS;

    const float4* W4 = (const float4*)W;
    for (int i = tid; i < (F_IN * F_H) / 4; i += 128)
        ((float4*)Ws)[i] = W4[i];
    const float4* x4 = (const float4*)x;
    for (int i = tid; i < nrow * (F_IN / 4); i += 128) {
        int r = i / (F_IN / 4), c = i % (F_IN / 4);
        float4 v = x4[(size_t)(row0 + r) * (F_IN / 4) + c];
        float* d = &xs[r * XPAD + c * 4];
        d[0] = v.x; d[1] = v.y; d[2] = v.z; d[3] = v.w;
    }
    __syncthreads();

    int rt = tid >> 2;
    int cq = tid & 3;
    int rbase = rt * 4;

    ull acc[4][4];
#pragma unroll
    for (int j = 0; j < 4; j++)
#pragma unroll
        for (int p = 0; p < 4; p++) acc[j][p] = 0ull;

    const ulonglong2* Wp = (const ulonglong2*)Ws;
    const float* xr = &xs[rbase * XPAD];

#pragma unroll 4
    for (int k = 0; k < F_IN; k++) {
        ulonglong2 wA = Wp[k * 8 + cq * 2];
        ulonglong2 wB = Wp[k * 8 + cq * 2 + 1];
#pragma unroll
        for (int j = 0; j < 4; j++) {
            ull a = dup2(xr[j * XPAD + k]);
            fma2(acc[j][0], a, wA.x);
            fma2(acc[j][1], a, wA.y);
            fma2(acc[j][2], a, wB.x);
            fma2(acc[j][3], a, wB.y);
        }
    }

    // epilogue: hs = h * dinv[row]; write g_hs and g_agg (self-loop init)
#pragma unroll
    for (int j = 0; j < 4; j++) {
        int row = row0 + rbase + j;
        if (row >= n_nodes) break;
        float dinv = rsqrtf(g_deg[row]);
        if (cq == 0) g_dinv[row] = dinv;
        float o[8];
#pragma unroll
        for (int p = 0; p < 4; p++) unpk(acc[j][p], o[p * 2], o[p * 2 + 1]);
        float4 v0 = {o[0]*dinv, o[1]*dinv, o[2]*dinv, o[3]*dinv};
        float4 v1 = {o[4]*dinv, o[5]*dinv, o[6]*dinv, o[7]*dinv};
        size_t off = (size_t)row * F_H + cq * 8;
        *(float4*)&g_hs [off]     = v0;  *(float4*)&g_hs [off + 4] = v1;
        *(float4*)&g_agg[off]     = v0;  *(float4*)&g_agg[off + 4] = v1;
    }
}

// ---------------- K4: scatter, 2 edges/thread, vector RED (dinv deferred) ----
// Thread handles edge eA = t>>3 and eB = eA + nhalf; lane g owns 4 features.
// Two independent gather->RED chains per thread (2x MLP vs 1 edge/thread).
__global__ void k_scatter(const void* __restrict__ edge_index, int n_edges) {
    int t = blockIdx.x * blockDim.x + threadIdx.x;
    int eA = t >> 3;
    int g = t & 7;
    int nhalf = (n_edges + 1) >> 1;
    if (eA >= nhalf) return;
    int is32 = g_is32;
    int eB = eA + nhalf;
    bool hasB = eB < n_edges;

    int srcA = edge_at(edge_index, eA, is32);
    int dstA = edge_at(edge_index, (size_t)n_edges + eA, is32);
    int srcB = 0, dstB = 0;
    if (hasB) {
        srcB = edge_at(edge_index, eB, is32);
        dstB = edge_at(edge_index, (size_t)n_edges + eB, is32);
    }

    const float4* hs4 = (const float4*)g_hs;
    float4 vA = __ldg(&hs4[(size_t)srcA * 8 + g]);
    float4 vB;
    if (hasB) vB = __ldg(&hs4[(size_t)srcB * 8 + g]);

    float* pA = &g_agg[(size_t)dstA * F_H + g * 4];
    asm volatile("red.global.add.v4.f32 [%0], {%1, %2, %3, %4};"
                 :: "l"(pA), "f"(vA.x), "f"(vA.y), "f"(vA.z), "f"(vA.w)
                 : "memory");
    if (hasB) {
        float* pB = &g_agg[(size_t)dstB * F_H + g * 4];
        asm volatile("red.global.add.v4.f32 [%0], {%1, %2, %3, %4};"
                     :: "l"(pB), "f"(vB.x), "f"(vB.y), "f"(vB.z), "f"(vB.w)
                     : "memory");
    }
}

// ---------------- K5: dinv scale + bias + relu + MLP + log_softmax -----------
__global__ void k_mlp(const float* __restrict__ b_conv,
                      const float* __restrict__ W1, const float* __restrict__ b1,
                      const float* __restrict__ W2, const float* __restrict__ b2,
                      const float* __restrict__ W3, const float* __restrict__ b3,
                      float* __restrict__ out, int n_nodes) {
    __shared__ float sW1[32 * 16], sb1[16];
    __shared__ float sW2[16 * 8],  sb2[8];
    __shared__ float sW3[8 * 10],  sb3[10];
    __shared__ float sbc[32];
    int tid = threadIdx.x;
    for (int i = tid; i < 32 * 16; i += blockDim.x) sW1[i] = W1[i];
    for (int i = tid; i < 16 * 8;  i += blockDim.x) sW2[i] = W2[i];
    for (int i = tid; i < 8 * 10;  i += blockDim.x) sW3[i] = W3[i];
    if (tid < 16) sb1[tid] = b1[tid];
    if (tid < 8)  sb2[tid] = b2[tid];
    if (tid < 10) sb3[tid] = b3[tid];
    if (tid < 32) sbc[tid] = b_conv[tid];
    __syncthreads();

    int node = blockIdx.x * blockDim.x + tid;
    if (node >= n_nodes) return;

    float dinv = g_dinv[node];
    float a[32];
    const float4* ag4 = (const float4*)(&g_agg[(size_t)node * F_H]);
#pragma unroll
    for (int q = 0; q < 8; q++) {
        float4 v = ag4[q];
        a[q * 4 + 0] = fmaxf(fmaf(v.x, dinv, sbc[q * 4 + 0]), 0.0f);
        a[q * 4 + 1] = fmaxf(fmaf(v.y, dinv, sbc[q * 4 + 1]), 0.0f);
        a[q * 4 + 2] = fmaxf(fmaf(v.z, dinv, sbc[q * 4 + 2]), 0.0f);
        a[q * 4 + 3] = fmaxf(fmaf(v.w, dinv, sbc[q * 4 + 3]), 0.0f);
    }

    float h1[16];
#pragma unroll
    for (int j = 0; j < 16; j++) {
        float s = sb1[j];
#pragma unroll
        for (int k = 0; k < 32; k++) s = fmaf(a[k], sW1[k * 16 + j], s);
        h1[j] = fmaxf(s, 0.0f);
    }
    float h2[8];
#pragma unroll
    for (int j = 0; j < 8; j++) {
        float s = sb2[j];
#pragma unroll
        for (int k = 0; k < 16; k++) s = fmaf(h1[k], sW2[k * 8 + j], s);
        h2[j] = fmaxf(s, 0.0f);
    }
    float z[10];
#pragma unroll
    for (int j = 0; j < 10; j++) {
        float s = sb3[j];
#pragma unroll
        for (int k = 0; k < 8; k++) s = fmaf(h2[k], sW3[k * 10 + j], s);
        z[j] = s;
    }
    float m = z[0];
#pragma unroll
    for (int j = 1; j < 10; j++) m = fmaxf(m, z[j]);
    float sum = 0.0f;
#pragma unroll
    for (int j = 0; j < 10; j++) sum += expf(z[j] - m);
    float lse = logf(sum) + m;
    float* op = out + (size_t)node * 10;
#pragma unroll
    for (int j = 0; j < 10; j++) op[j] = z[j] - lse;
}

// ---------------- launch -----------------------------------------------------
extern "C" void kernel_launch(void* const* d_in, const int* in_sizes, int n_in,
                              void* d_out, int out_size) {
    const float* x          = (const float*)d_in[0];
    const void*  edge_index = (const void*)d_in[1];
    const float* W_conv = (const float*)d_in[3];
    const float* b_conv = (const float*)d_in[4];
    const float* W1 = (const float*)d_in[5];
    const float* b1 = (const float*)d_in[6];
    const float* W2 = (const float*)d_in[7];
    const float* b2 = (const float*)d_in[8];
    const float* W3 = (const float*)d_in[9];
    const float* b3 = (const float*)d_in[10];
    float* out = (float*)d_out;

    int n_nodes = in_sizes[0] / F_IN;
    int n_edges = in_sizes[1] / 2;

    const int gemm_smem = (GROWS * XPAD + F_IN * F_H) * (int)sizeof(float); // 64 KB
    static int attr_done = 0;
    if (!attr_done) {
        cudaFuncSetAttribute(k_gemm, cudaFuncAttributeMaxDynamicSharedMemorySize,
                             gemm_smem);
        attr_done = 1;
    }

    k_init_deg<<<(n_nodes + 255) / 256, 256>>>(edge_index, in_sizes[1], n_nodes);
    k_degree<<<(n_edges + 255) / 256, 256>>>(edge_index, n_edges);

    k_gemm<<<(n_nodes + GROWS - 1) / GROWS, 128, gemm_smem>>>(x, W_conv, n_nodes);

    int nhalf = (n_edges + 1) >> 1;
    long long scatter_threads = (long long)nhalf * 8;
    k_scatter<<<(int)((scatter_threads + 255) / 256), 256>>>(edge_index, n_edges);

    k_mlp<<<(n_nodes + 127) / 128, 128>>>(b_conv, W1, b1, W2, b2, W3, b3,
                                          out, n_nodes);
}